// round 14
// baseline (speedup 1.0000x reference)
#include <cuda_runtime.h>
#include <cuda_fp16.h>
#include <cstdint>

#define BATCH 512
#define T 128
#define C 384
#define H 6
#define D 64
#define HD 384
#define NQKV 1152

// ---------------- scratch (device globals; no runtime allocation) ----------------
__device__ __align__(256) __half g_xhi[(size_t)BATCH * T * C];
__device__ __align__(256) __half g_wthi[(size_t)NQKV * C];    // [n][k]
__device__ __align__(256) __half g_wpthi[(size_t)HD * C];     // [n][k] = Wp[k][n]
__device__ __align__(256) __half g_atthi[(size_t)BATCH * T * HD];
// q (pre-scaled D^-1/2), k, v single fp16; all [b][h][t][d]
__device__ __align__(256) __half g_q[(size_t)BATCH * H * T * D];
__device__ __align__(256) __half g_k[(size_t)BATCH * H * T * D];
__device__ __align__(256) __half g_v[(size_t)BATCH * H * T * D];

// ---------------- helpers (baseline PTX, compute_103-safe) ----------------
__device__ __forceinline__ uint32_t smem_u32(const void* p) {
    uint32_t a;
    asm("{ .reg .u64 t; cvta.to.shared.u64 t, %1; cvt.u32.u64 %0, t; }" : "=r"(a) : "l"(p));
    return a;
}
__device__ __forceinline__ void ldsm4(uint32_t* r, uint32_t addr) {
    asm volatile("ldmatrix.sync.aligned.m8n8.x4.shared.b16 {%0,%1,%2,%3}, [%4];"
        : "=r"(r[0]), "=r"(r[1]), "=r"(r[2]), "=r"(r[3]) : "r"(addr));
}
__device__ __forceinline__ void ldsm4t(uint32_t* r, uint32_t addr) {
    asm volatile("ldmatrix.sync.aligned.m8n8.x4.trans.shared.b16 {%0,%1,%2,%3}, [%4];"
        : "=r"(r[0]), "=r"(r[1]), "=r"(r[2]), "=r"(r[3]) : "r"(addr));
}
// fp16 MMA, fp32 accum
__device__ __forceinline__ void mma16816f(float* c, const uint32_t* a, const uint32_t* b) {
    asm volatile("mma.sync.aligned.m16n8k16.row.col.f32.f16.f16.f32 "
        "{%0,%1,%2,%3}, {%4,%5,%6,%7}, {%8,%9}, {%0,%1,%2,%3};"
        : "+f"(c[0]), "+f"(c[1]), "+f"(c[2]), "+f"(c[3])
        : "r"(a[0]), "r"(a[1]), "r"(a[2]), "r"(a[3]), "r"(b[0]), "r"(b[1]));
}
__device__ __forceinline__ void cpa16(uint32_t dst, const void* src) {
    asm volatile("cp.async.cg.shared.global [%0], [%1], 16;" :: "r"(dst), "l"(src));
}
#define CPA_COMMIT() asm volatile("cp.async.commit_group;" ::: "memory")
#define CPA_WAIT2()  asm volatile("cp.async.wait_group 2;" ::: "memory")
#define CPA_WAIT1()  asm volatile("cp.async.wait_group 1;" ::: "memory")
#define CPA_WAIT0()  asm volatile("cp.async.wait_group 0;" ::: "memory")

__device__ __forceinline__ uint32_t pack_f16x2(float a, float b) {
    __half2 h = __floats2half2_rn(a, b);
    return *(uint32_t*)&h;
}

// =================================================================================
// Fused conversion kernel: x -> fp16, Wq/Wk/Wv -> wt[n][k], Wp -> wpt[n][k]
// =================================================================================
#define NB_X  ((BATCH * T * C / 4) / 256)          // 24576
#define NB_W  ((NQKV * C + 255) / 256)             // 1728
#define NB_WP ((HD * C + 255) / 256)               // 576

__global__ void conv_all_kernel(const float* __restrict__ x,
                                const float* __restrict__ Wq, const float* __restrict__ Wk,
                                const float* __restrict__ Wv, const float* __restrict__ Wp)
{
    const int bid = blockIdx.x;
    if (bid < NB_X) {
        size_t i = ((size_t)bid * 256 + threadIdx.x) * 4;
        float4 v = *(const float4*)(x + i);
        *(uint32_t*)(g_xhi + i)     = pack_f16x2(v.x, v.y);
        *(uint32_t*)(g_xhi + i + 2) = pack_f16x2(v.z, v.w);
    } else if (bid < NB_X + NB_W) {
        int idx = (bid - NB_X) * 256 + threadIdx.x;   // n*C + k
        if (idx >= NQKV * C) return;
        int n = idx / C, k = idx - n * C;
        int which = n / HD, rem = n - which * HD;
        int h = rem >> 6, d = rem & 63;
        const float* W = (which == 0) ? Wq : (which == 1) ? Wk : Wv;
        g_wthi[idx] = __float2half_rn(W[((size_t)h * C + k) * D + d]);
    } else {
        int idx = (bid - NB_X - NB_W) * 256 + threadIdx.x;   // n*C + k
        if (idx >= HD * C) return;
        int n = idx / C, k = idx - n * C;
        g_wpthi[idx] = __float2half_rn(Wp[(size_t)k * C + n]);
    }
}

// =================================================================================
// Pure fp16 GEMM, 2 batches per CTA in one continuous 12-chunk pipeline.
// Stage (32KB): A@0 (16K), B@16K (16K); 3 stages = 96KB; 2 CTAs/SM.
// grid = (ntiles, BATCH/2).
// =================================================================================
#define STAGE_BYTES 32768
#define GEMM_SMEM (3 * STAGE_BYTES)

template <bool PROJ>
__global__ __launch_bounds__(256, 2)
void mma_gemm(const float* __restrict__ bp, float* __restrict__ out)
{
    extern __shared__ __align__(1024) char sm[];
    const uint32_t smb = smem_u32(sm);
    const int tid = threadIdx.x, wid = tid >> 5, lane = tid & 31;
    const int b0 = blockIdx.y * 2, n0 = blockIdx.x * 128;
    const int wm = (wid >> 2) * 64;     // 0,64
    const int wn = (wid & 3) * 32;      // 0,32,64,96

    const __half* __restrict__ Asrc = (PROJ ? g_atthi : g_xhi);
    const __half* __restrict__ Bhi  = (PROJ ? g_wpthi : g_wthi) + (size_t)n0 * C;

    const int l_row = tid >> 3;          // 0..31
    const int l_seg = tid & 7;

    // total-chunk index tc in [0,12): batch bi = tc/6, k-chunk c = tc%6
    auto load_tc = [&](int tc) {
        const int bi = tc / 6;
        const int c0 = (tc % 6) * 64;
        const __half* __restrict__ A = Asrc + (size_t)(b0 + bi) * T * C;
        const uint32_t sb = smb + (tc % 3) * STAGE_BYTES;
#pragma unroll
        for (int p = 0; p < 4; p++) {
            const int row = l_row + p * 32;
            const uint32_t doff = (uint32_t)(row * 128 + ((l_seg ^ (row & 7)) << 4));
            const size_t soff = (size_t)row * C + c0 + l_seg * 8;
            cpa16(sb + doff,         A + soff);
            cpa16(sb + 16384 + doff, Bhi + soff);
        }
        CPA_COMMIT();
    };

    const int rA  = (lane & 7) + ((lane >> 3) & 1) * 8;
    const int khA = lane >> 4;
    const int swA = rA & 7;
    const int rB  = (lane & 7) + (lane >> 4) * 8;
    const int khB = (lane >> 3) & 1;
    const int swB = rB & 7;
    const int qrow = lane >> 2;
    const int qcol = (lane & 3) * 2;

    load_tc(0);
    load_tc(1);
    load_tc(2);

    float acc[4][4][4];

    for (int bi = 0; bi < 2; bi++) {
#pragma unroll
        for (int i = 0; i < 4; i++)
#pragma unroll
            for (int j = 0; j < 4; j++)
#pragma unroll
                for (int e = 0; e < 4; e++) acc[i][j][e] = 0.f;

        for (int c = 0; c < 6; c++) {
            const int tc = bi * 6 + c;
            if (tc < 10) CPA_WAIT2(); else if (tc == 10) CPA_WAIT1(); else CPA_WAIT0();
            __syncthreads();

            const uint32_t sb = smb + (tc % 3) * STAGE_BYTES;
            const uint32_t aBase = sb + (uint32_t)((wm + rA) * 128);
            const uint32_t bBase = sb + 16384 + (uint32_t)((wn + rB) * 128);

#pragma unroll
            for (int ks = 0; ks < 4; ks++) {
                const uint32_t aoff = (uint32_t)(((ks * 2 + khA) ^ swA) << 4);
                const uint32_t boff = (uint32_t)(((ks * 2 + khB) ^ swB) << 4);
                uint32_t ah[4][4], bh[2][4];
                ldsm4(ah[0], aBase + aoff);
                ldsm4(bh[0], bBase + boff);
                ldsm4(ah[1], aBase + 2048 + aoff);
                ldsm4(bh[1], bBase + 2048 + boff);
                mma16816f(acc[0][0], ah[0], &bh[0][0]);
                mma16816f(acc[0][1], ah[0], &bh[0][2]);
                ldsm4(ah[2], aBase + 4096 + aoff);
                mma16816f(acc[0][2], ah[0], &bh[1][0]);
                mma16816f(acc[0][3], ah[0], &bh[1][2]);
                ldsm4(ah[3], aBase + 6144 + aoff);
                mma16816f(acc[1][0], ah[1], &bh[0][0]);
                mma16816f(acc[1][1], ah[1], &bh[0][2]);
                mma16816f(acc[1][2], ah[1], &bh[1][0]);
                mma16816f(acc[1][3], ah[1], &bh[1][2]);
#pragma unroll
                for (int mf = 2; mf < 4; mf++) {
                    mma16816f(acc[mf][0], ah[mf], &bh[0][0]);
                    mma16816f(acc[mf][1], ah[mf], &bh[0][2]);
                    mma16816f(acc[mf][2], ah[mf], &bh[1][0]);
                    mma16816f(acc[mf][3], ah[mf], &bh[1][2]);
                }
            }
            __syncthreads();
            if (tc + 3 < 12) load_tc(tc + 3);
        }

        // ---------------- epilogue for batch bi ----------------
        const int b = b0 + bi;
        if (PROJ) {
#pragma unroll
            for (int mf = 0; mf < 4; mf++) {
#pragma unroll
                for (int nf = 0; nf < 4; nf++) {
                    const int row = wm + mf * 16 + qrow;
                    const int col = n0 + wn + nf * 8 + qcol;
                    const float2 bb = *(const float2*)(bp + col);
                    float* p0 = out + ((size_t)b * T + row) * HD + col;
                    float* p1 = out + ((size_t)b * T + row + 8) * HD + col;
                    *(float2*)p0 = make_float2(acc[mf][nf][0] + bb.x, acc[mf][nf][1] + bb.y);
                    *(float2*)p1 = make_float2(acc[mf][nf][2] + bb.x, acc[mf][nf][3] + bb.y);
                }
            }
        } else {
            const int which = blockIdx.x / 3;       // 0=q,1=k,2=v
            const int rem0 = (blockIdx.x % 3) * 128;
            __half* dst = (which == 0) ? g_q : (which == 1) ? g_k : g_v;
            const float scale = (which == 0) ? 0.125f : 1.0f;
#pragma unroll
            for (int mf = 0; mf < 4; mf++) {
#pragma unroll
                for (int nf = 0; nf < 4; nf++) {
                    const int row = wm + mf * 16 + qrow;
                    const int rem = rem0 + wn + nf * 8 + qcol;
                    const int hh = rem >> 6, dd = rem & 63;
                    const size_t o0 = (((size_t)(b * H + hh) * T) + row) * D + dd;
                    *(uint32_t*)(dst + o0) =
                        pack_f16x2(acc[mf][nf][0] * scale, acc[mf][nf][1] * scale);
                    *(uint32_t*)(dst + o0 + 8 * D) =
                        pack_f16x2(acc[mf][nf][2] * scale, acc[mf][nf][3] * scale);
                }
            }
        }
    }
}

// =================================================================================
// MMA attention per (b, h): Q/K/V/P single fp16, fp32 accum.
// V loaded as a second cp.async group, overlapped with the S computation.
// smem: q@0 (16K), k@16K, v@32K => 48KB; 2 CTAs/SM.
// =================================================================================
#define ATTN_SMEM 49152

__global__ __launch_bounds__(256, 2)
void attn_mma()
{
    extern __shared__ __align__(1024) char sm[];
    const uint32_t smb = smem_u32(sm);
    const int tid = threadIdx.x, w = tid >> 5, lane = tid & 31;
    const int b = blockIdx.x, h = blockIdx.y;
    const int rb = (w < 4) ? w : (11 - w);     // row-block; SMSP pairs balanced

    const size_t blk = (size_t)(b * H + h) * (T * D);
    {
        const int seg = tid & 7;
#pragma unroll
        for (int p = 0; p < 4; p++) {
            const int row = (tid + p * 256) >> 3;          // 0..127
            const uint32_t doff = (uint32_t)(row * 128 + ((seg ^ (row & 7)) << 4));
            const size_t soff = blk + (size_t)row * D + seg * 8;
            cpa16(smb + doff,         g_q + soff);
            cpa16(smb + 16384 + doff, g_k + soff);
        }
        CPA_COMMIT();
#pragma unroll
        for (int p = 0; p < 4; p++) {
            const int row = (tid + p * 256) >> 3;
            const uint32_t doff = (uint32_t)(row * 128 + ((seg ^ (row & 7)) << 4));
            const size_t soff = blk + (size_t)row * D + seg * 8;
            cpa16(smb + 32768 + doff, g_v + soff);
        }
        CPA_COMMIT();
    }
    CPA_WAIT1();            // q,k complete; v still in flight
    __syncthreads();

    const int rA  = (lane & 7) + ((lane >> 3) & 1) * 8;
    const int khA = lane >> 4;
    const int swA = rA & 7;
    const int rB  = (lane & 7) + (lane >> 4) * 8;
    const int khB = (lane >> 3) & 1;
    const int swB = rB & 7;

    const uint32_t aQ = smb + (uint32_t)((rb * 16 + rA) * 128);

    // ---------------- S = Q @ K^T (single term, causal block-skip) ----------------
    float S[16][4];
#pragma unroll
    for (int i = 0; i < 16; i++)
#pragma unroll
        for (int e = 0; e < 4; e++) S[i][e] = 0.f;

#pragma unroll
    for (int ks = 0; ks < 4; ks++) {
        uint32_t qh[4];
        const uint32_t aoff = (uint32_t)(((ks * 2 + khA) ^ swA) << 4);
        ldsm4(qh, aQ + aoff);
        const uint32_t boff = (uint32_t)(((ks * 2 + khB) ^ swB) << 4);
#pragma unroll
        for (int g = 0; g < 8; g += 2) {
            if (g > rb) break;
            uint32_t kh0[4];
            const uint32_t bb0 = smb + 16384 + (uint32_t)((g * 16 + rB) * 128);
            ldsm4(kh0, bb0 + boff);
            const bool g1ok = (g + 1) <= rb;
            uint32_t kh1[4];
            if (g1ok) {
                const uint32_t bb1 = smb + 16384 + (uint32_t)(((g + 1) * 16 + rB) * 128);
                ldsm4(kh1, bb1 + boff);
            }
            mma16816f(S[2 * g],     qh, &kh0[0]);
            mma16816f(S[2 * g + 1], qh, &kh0[2]);
            if (g1ok) {
                mma16816f(S[2 * g + 2], qh, &kh1[0]);
                mma16816f(S[2 * g + 3], qh, &kh1[2]);
            }
        }
    }

    // ---------------- softmax exponentials (q pre-scaled by D^-1/2) ----------
    const int row0 = rb * 16 + (lane >> 2);
    const int row1 = row0 + 8;
    const int colb = 2 * (lane & 3);
    float sum0 = 0.f, sum1 = 0.f;
#pragma unroll
    for (int nf = 0; nf < 16; nf++) {
        if (nf > 2 * rb + 1) break;
        const int c0 = nf * 8 + colb, c1 = c0 + 1;
        float e00 = (c0 <= row0) ? __expf(S[nf][0]) : 0.f;
        float e01 = (c1 <= row0) ? __expf(S[nf][1]) : 0.f;
        float e10 = (c0 <= row1) ? __expf(S[nf][2]) : 0.f;
        float e11 = (c1 <= row1) ? __expf(S[nf][3]) : 0.f;
        S[nf][0] = e00; S[nf][1] = e01; S[nf][2] = e10; S[nf][3] = e11;
        sum0 += e00 + e01;
        sum1 += e10 + e11;
    }
    sum0 += __shfl_xor_sync(0xFFFFFFFFu, sum0, 1);
    sum0 += __shfl_xor_sync(0xFFFFFFFFu, sum0, 2);
    sum1 += __shfl_xor_sync(0xFFFFFFFFu, sum1, 1);
    sum1 += __shfl_xor_sync(0xFFFFFFFFu, sum1, 2);
    const float inv0 = 1.0f / sum0;
    const float inv1 = 1.0f / sum1;

    // v must be fully resident (all threads' copies) before ldmatrix reads it
    CPA_WAIT0();
    __syncthreads();

    // ---------------- O = (raw P) @ V; P single fp16, V single fp16 --------
    float O[8][4];
#pragma unroll
    for (int i = 0; i < 8; i++)
#pragma unroll
        for (int e = 0; e < 4; e++) O[i][e] = 0.f;

    const int mT = lane >> 3;
    const int rT = lane & 7;

#pragma unroll
    for (int ks = 0; ks < 8; ks++) {
        if (ks > rb) break;
        const int srow = ks * 16 + (mT & 1) * 8 + rT;
        const uint32_t rowOff = (uint32_t)(srow * 128);
        uint32_t vh[4][4];
        {
            const int dseg0 = (mT >> 1);
            const uint32_t a0 = rowOff + (uint32_t)(((dseg0 ^ (srow & 7)) << 4));
            ldsm4t(vh[0], smb + 32768 + a0);
        }
        uint32_t phi[4];
        phi[0] = pack_f16x2(S[2 * ks][0],     S[2 * ks][1]);
        phi[1] = pack_f16x2(S[2 * ks][2],     S[2 * ks][3]);
        phi[2] = pack_f16x2(S[2 * ks + 1][0], S[2 * ks + 1][1]);
        phi[3] = pack_f16x2(S[2 * ks + 1][2], S[2 * ks + 1][3]);
#pragma unroll
        for (int g = 1; g < 4; g++) {
            const int dseg = g * 2 + (mT >> 1);
            const uint32_t addr = rowOff + (uint32_t)(((dseg ^ (srow & 7)) << 4));
            ldsm4t(vh[g], smb + 32768 + addr);
            mma16816f(O[2 * (g - 1)],     phi, &vh[g - 1][0]);
            mma16816f(O[2 * (g - 1) + 1], phi, &vh[g - 1][2]);
        }
        mma16816f(O[6], phi, &vh[3][0]);
        mma16816f(O[7], phi, &vh[3][2]);
    }

    // ---------------- epilogue: normalize, att fp16 [b][t][h*64+d] ---------
    const size_t obase = (size_t)b * T * HD + h * D;
#pragma unroll
    for (int nf = 0; nf < 8; nf++) {
        const int d0 = nf * 8 + colb;
        *(uint32_t*)(g_atthi + obase + (size_t)row0 * HD + d0) =
            pack_f16x2(O[nf][0] * inv0, O[nf][1] * inv0);
        *(uint32_t*)(g_atthi + obase + (size_t)row1 * HD + d0) =
            pack_f16x2(O[nf][2] * inv1, O[nf][3] * inv1);
    }
}

// =================================================================================
extern "C" void kernel_launch(void* const* d_in, const int* in_sizes, int n_in,
                              void* d_out, int out_size)
{
    (void)in_sizes; (void)n_in; (void)out_size;
    const float* x  = (const float*)d_in[0];
    const float* Wq = (const float*)d_in[1];
    const float* Wk = (const float*)d_in[2];
    const float* Wv = (const float*)d_in[3];
    const float* Wp = (const float*)d_in[4];
    const float* bp = (const float*)d_in[5];
    float* out = (float*)d_out;

    cudaFuncSetAttribute(mma_gemm<false>, cudaFuncAttributeMaxDynamicSharedMemorySize, GEMM_SMEM);
    cudaFuncSetAttribute(mma_gemm<true>,  cudaFuncAttributeMaxDynamicSharedMemorySize, GEMM_SMEM);
    cudaFuncSetAttribute(attn_mma, cudaFuncAttributeMaxDynamicSharedMemorySize, ATTN_SMEM);

    conv_all_kernel<<<NB_X + NB_W + NB_WP, 256>>>(x, Wq, Wk, Wv, Wp);

    mma_gemm<false><<<dim3(9, BATCH / 2), 256, GEMM_SMEM>>>(nullptr, nullptr);
    attn_mma<<<dim3(BATCH, H), 256, ATTN_SMEM>>>();
    mma_gemm<true><<<dim3(3, BATCH / 2), 256, GEMM_SMEM>>>(bp, out);
}

// round 15
// speedup vs baseline: 1.0433x; 1.0433x over previous
#include <cuda_runtime.h>
#include <cuda_fp16.h>
#include <cstdint>

#define BATCH 512
#define T 128
#define C 384
#define H 6
#define D 64
#define HD 384
#define NQKV 1152

// ---------------- scratch (device globals; no runtime allocation) ----------------
__device__ __align__(256) __half g_xhi[(size_t)BATCH * T * C];
__device__ __align__(256) __half g_wthi[(size_t)NQKV * C];    // [n][k]
__device__ __align__(256) __half g_wpthi[(size_t)HD * C];     // [n][k] = Wp[k][n]
__device__ __align__(256) __half g_atthi[(size_t)BATCH * T * HD];
// q (pre-scaled D^-1/2), k, v single fp16; all [b][h][t][d]
__device__ __align__(256) __half g_q[(size_t)BATCH * H * T * D];
__device__ __align__(256) __half g_k[(size_t)BATCH * H * T * D];
__device__ __align__(256) __half g_v[(size_t)BATCH * H * T * D];

// ---------------- helpers (baseline PTX, compute_103-safe) ----------------
__device__ __forceinline__ uint32_t smem_u32(const void* p) {
    uint32_t a;
    asm("{ .reg .u64 t; cvta.to.shared.u64 t, %1; cvt.u32.u64 %0, t; }" : "=r"(a) : "l"(p));
    return a;
}
__device__ __forceinline__ void ldsm4(uint32_t* r, uint32_t addr) {
    asm volatile("ldmatrix.sync.aligned.m8n8.x4.shared.b16 {%0,%1,%2,%3}, [%4];"
        : "=r"(r[0]), "=r"(r[1]), "=r"(r[2]), "=r"(r[3]) : "r"(addr));
}
__device__ __forceinline__ void ldsm4t(uint32_t* r, uint32_t addr) {
    asm volatile("ldmatrix.sync.aligned.m8n8.x4.trans.shared.b16 {%0,%1,%2,%3}, [%4];"
        : "=r"(r[0]), "=r"(r[1]), "=r"(r[2]), "=r"(r[3]) : "r"(addr));
}
// fp16 MMA, fp32 accum
__device__ __forceinline__ void mma16816f(float* c, const uint32_t* a, const uint32_t* b) {
    asm volatile("mma.sync.aligned.m16n8k16.row.col.f32.f16.f16.f32 "
        "{%0,%1,%2,%3}, {%4,%5,%6,%7}, {%8,%9}, {%0,%1,%2,%3};"
        : "+f"(c[0]), "+f"(c[1]), "+f"(c[2]), "+f"(c[3])
        : "r"(a[0]), "r"(a[1]), "r"(a[2]), "r"(a[3]), "r"(b[0]), "r"(b[1]));
}
__device__ __forceinline__ void cpa16(uint32_t dst, const void* src) {
    asm volatile("cp.async.cg.shared.global [%0], [%1], 16;" :: "r"(dst), "l"(src));
}
#define CPA_COMMIT() asm volatile("cp.async.commit_group;" ::: "memory")
#define CPA_WAIT2()  asm volatile("cp.async.wait_group 2;" ::: "memory")
#define CPA_WAIT1()  asm volatile("cp.async.wait_group 1;" ::: "memory")
#define CPA_WAIT0()  asm volatile("cp.async.wait_group 0;" ::: "memory")

__device__ __forceinline__ uint32_t pack_f16x2(float a, float b) {
    __half2 h = __floats2half2_rn(a, b);
    return *(uint32_t*)&h;
}

// =================================================================================
// Fused conversion kernel: x -> fp16, Wq/Wk/Wv -> wt[n][k], Wp -> wpt[n][k]
// =================================================================================
#define NB_X  ((BATCH * T * C / 4) / 256)          // 24576
#define NB_W  ((NQKV * C + 255) / 256)             // 1728
#define NB_WP ((HD * C + 255) / 256)               // 576

__global__ void conv_all_kernel(const float* __restrict__ x,
                                const float* __restrict__ Wq, const float* __restrict__ Wk,
                                const float* __restrict__ Wv, const float* __restrict__ Wp)
{
    const int bid = blockIdx.x;
    if (bid < NB_X) {
        size_t i = ((size_t)bid * 256 + threadIdx.x) * 4;
        float4 v = *(const float4*)(x + i);
        *(uint32_t*)(g_xhi + i)     = pack_f16x2(v.x, v.y);
        *(uint32_t*)(g_xhi + i + 2) = pack_f16x2(v.z, v.w);
    } else if (bid < NB_X + NB_W) {
        int idx = (bid - NB_X) * 256 + threadIdx.x;   // n*C + k
        if (idx >= NQKV * C) return;
        int n = idx / C, k = idx - n * C;
        int which = n / HD, rem = n - which * HD;
        int h = rem >> 6, d = rem & 63;
        const float* W = (which == 0) ? Wq : (which == 1) ? Wk : Wv;
        g_wthi[idx] = __float2half_rn(W[((size_t)h * C + k) * D + d]);
    } else {
        int idx = (bid - NB_X - NB_W) * 256 + threadIdx.x;   // n*C + k
        if (idx >= HD * C) return;
        int n = idx / C, k = idx - n * C;
        g_wpthi[idx] = __float2half_rn(Wp[(size_t)k * C + n]);
    }
}

// =================================================================================
// QKV GEMM (R13-proven): Y[128x128] = x[128x384] @ wt^T, 3-stage pipeline,
// stage 32KB, 2 CTAs/SM, grid (9, BATCH).
// =================================================================================
#define STAGE_BYTES 32768
#define GEMM_SMEM (3 * STAGE_BYTES)

__global__ __launch_bounds__(256, 2)
void qkv_gemm()
{
    extern __shared__ __align__(1024) char sm[];
    const uint32_t smb = smem_u32(sm);
    const int tid = threadIdx.x, wid = tid >> 5, lane = tid & 31;
    const int b = blockIdx.y, n0 = blockIdx.x * 128;
    const int wm = (wid >> 2) * 64;     // 0,64
    const int wn = (wid & 3) * 32;      // 0,32,64,96

    const __half* __restrict__ Ahi = g_xhi + (size_t)b * T * C;
    const __half* __restrict__ Bhi = g_wthi + (size_t)n0 * C;

    const int l_row = tid >> 3;
    const int l_seg = tid & 7;

    auto load_chunk = [&](int c) {
        const int c0 = c * 64;
        const uint32_t sb = smb + (c % 3) * STAGE_BYTES;
#pragma unroll
        for (int p = 0; p < 4; p++) {
            const int row = l_row + p * 32;
            const uint32_t doff = (uint32_t)(row * 128 + ((l_seg ^ (row & 7)) << 4));
            const size_t soff = (size_t)row * C + c0 + l_seg * 8;
            cpa16(sb + doff,         Ahi + soff);
            cpa16(sb + 16384 + doff, Bhi + soff);
        }
        CPA_COMMIT();
    };

    float acc[4][4][4];
#pragma unroll
    for (int i = 0; i < 4; i++)
#pragma unroll
        for (int j = 0; j < 4; j++)
#pragma unroll
            for (int e = 0; e < 4; e++) acc[i][j][e] = 0.f;

    const int rA  = (lane & 7) + ((lane >> 3) & 1) * 8;
    const int khA = lane >> 4;
    const int swA = rA & 7;
    const int rB  = (lane & 7) + (lane >> 4) * 8;
    const int khB = (lane >> 3) & 1;
    const int swB = rB & 7;

    load_chunk(0);
    load_chunk(1);
    load_chunk(2);

    for (int c = 0; c < 6; c++) {
        if (c < 4) CPA_WAIT2(); else if (c == 4) CPA_WAIT1(); else CPA_WAIT0();
        __syncthreads();

        const uint32_t sb = smb + (c % 3) * STAGE_BYTES;
        const uint32_t aBase = sb + (uint32_t)((wm + rA) * 128);
        const uint32_t bBase = sb + 16384 + (uint32_t)((wn + rB) * 128);

#pragma unroll
        for (int ks = 0; ks < 4; ks++) {
            const uint32_t aoff = (uint32_t)(((ks * 2 + khA) ^ swA) << 4);
            const uint32_t boff = (uint32_t)(((ks * 2 + khB) ^ swB) << 4);
            uint32_t ah[4][4], bh[2][4];
            ldsm4(ah[0], aBase + aoff);
            ldsm4(bh[0], bBase + boff);
            ldsm4(ah[1], aBase + 2048 + aoff);
            ldsm4(bh[1], bBase + 2048 + boff);
            mma16816f(acc[0][0], ah[0], &bh[0][0]);
            mma16816f(acc[0][1], ah[0], &bh[0][2]);
            ldsm4(ah[2], aBase + 4096 + aoff);
            mma16816f(acc[0][2], ah[0], &bh[1][0]);
            mma16816f(acc[0][3], ah[0], &bh[1][2]);
            ldsm4(ah[3], aBase + 6144 + aoff);
            mma16816f(acc[1][0], ah[1], &bh[0][0]);
            mma16816f(acc[1][1], ah[1], &bh[0][2]);
            mma16816f(acc[1][2], ah[1], &bh[1][0]);
            mma16816f(acc[1][3], ah[1], &bh[1][2]);
#pragma unroll
            for (int mf = 2; mf < 4; mf++) {
                mma16816f(acc[mf][0], ah[mf], &bh[0][0]);
                mma16816f(acc[mf][1], ah[mf], &bh[0][2]);
                mma16816f(acc[mf][2], ah[mf], &bh[1][0]);
                mma16816f(acc[mf][3], ah[mf], &bh[1][2]);
            }
        }
        __syncthreads();
        if (c + 3 < 6) load_chunk(c + 3);
    }

    const int qrow = lane >> 2;
    const int qcol = (lane & 3) * 2;
    const int which = blockIdx.x / 3;       // 0=q,1=k,2=v
    const int rem0 = (blockIdx.x % 3) * 128;
    __half* dst = (which == 0) ? g_q : (which == 1) ? g_k : g_v;
    const float scale = (which == 0) ? 0.125f : 1.0f;
#pragma unroll
    for (int mf = 0; mf < 4; mf++) {
#pragma unroll
        for (int nf = 0; nf < 4; nf++) {
            const int row = wm + mf * 16 + qrow;
            const int rem = rem0 + wn + nf * 8 + qcol;
            const int hh = rem >> 6, dd = rem & 63;
            const size_t o0 = (((size_t)(b * H + hh) * T) + row) * D + dd;
            *(uint32_t*)(dst + o0) =
                pack_f16x2(acc[mf][nf][0] * scale, acc[mf][nf][1] * scale);
            *(uint32_t*)(dst + o0 + 8 * D) =
                pack_f16x2(acc[mf][nf][2] * scale, acc[mf][nf][3] * scale);
        }
    }
}

// =================================================================================
// Proj GEMM (R9-proven shape): Y[128x64] = att[128x384] @ wpt^T + bias.
// Stage 24KB (A16K, B8K), 2 stages = 48KB, 3 CTAs/SM, grid (6, BATCH).
// =================================================================================
#define PSTAGE_BYTES 24576
#define PROJ_SMEM (2 * PSTAGE_BYTES)

__global__ __launch_bounds__(256, 3)
void proj_gemm(const float* __restrict__ bp, float* __restrict__ out)
{
    extern __shared__ __align__(1024) char sm[];
    const uint32_t smb = smem_u32(sm);
    const int tid = threadIdx.x, wid = tid >> 5, lane = tid & 31;
    const int b = blockIdx.y, n0 = blockIdx.x * 64;
    const int wm = (wid >> 1) * 32;     // 0,32,64,96
    const int wn = (wid & 1) * 32;      // 0,32

    const __half* __restrict__ Ahi = g_atthi + (size_t)b * T * C;
    const __half* __restrict__ Bhi = g_wpthi + (size_t)n0 * C;

    const int l_row = tid >> 3;
    const int l_seg = tid & 7;

    auto load_chunk = [&](int c, int s) {
        const int c0 = c * 64;
        const uint32_t sb = smb + s * PSTAGE_BYTES;
#pragma unroll
        for (int p = 0; p < 4; p++) {
            const int row = l_row + p * 32;
            const uint32_t doff = (uint32_t)(row * 128 + ((l_seg ^ (row & 7)) << 4));
            cpa16(sb + doff, Ahi + (size_t)row * C + c0 + l_seg * 8);
        }
#pragma unroll
        for (int p = 0; p < 2; p++) {
            const int row = l_row + p * 32;   // 0..63
            const uint32_t doff = (uint32_t)(row * 128 + ((l_seg ^ (row & 7)) << 4));
            cpa16(sb + 16384 + doff, Bhi + (size_t)row * C + c0 + l_seg * 8);
        }
        CPA_COMMIT();
    };

    float acc[2][4][4];
#pragma unroll
    for (int i = 0; i < 2; i++)
#pragma unroll
        for (int j = 0; j < 4; j++)
#pragma unroll
            for (int e = 0; e < 4; e++) acc[i][j][e] = 0.f;

    const int rA  = (lane & 7) + ((lane >> 3) & 1) * 8;
    const int khA = lane >> 4;
    const int swA = rA & 7;
    const int rB  = (lane & 7) + (lane >> 4) * 8;
    const int khB = (lane >> 3) & 1;
    const int swB = rB & 7;

    load_chunk(0, 0);
    load_chunk(1, 1);

    for (int c = 0; c < 6; c++) {
        if (c == 5) CPA_WAIT0(); else CPA_WAIT1();
        __syncthreads();

        const uint32_t sb = smb + (c & 1) * PSTAGE_BYTES;
        const uint32_t aBase = sb + (uint32_t)((wm + rA) * 128);
        const uint32_t bBase = sb + 16384 + (uint32_t)((wn + rB) * 128);

#pragma unroll
        for (int ks = 0; ks < 4; ks++) {
            const uint32_t aoff = (uint32_t)(((ks * 2 + khA) ^ swA) << 4);
            const uint32_t boff = (uint32_t)(((ks * 2 + khB) ^ swB) << 4);
            uint32_t ah[2][4], bh[2][4];
            ldsm4(ah[0], aBase + aoff);
            ldsm4(bh[0], bBase + boff);
            ldsm4(ah[1], aBase + 2048 + aoff);
            ldsm4(bh[1], bBase + 2048 + boff);
            mma16816f(acc[0][0], ah[0], &bh[0][0]);
            mma16816f(acc[0][1], ah[0], &bh[0][2]);
            mma16816f(acc[0][2], ah[0], &bh[1][0]);
            mma16816f(acc[0][3], ah[0], &bh[1][2]);
            mma16816f(acc[1][0], ah[1], &bh[0][0]);
            mma16816f(acc[1][1], ah[1], &bh[0][2]);
            mma16816f(acc[1][2], ah[1], &bh[1][0]);
            mma16816f(acc[1][3], ah[1], &bh[1][2]);
        }
        __syncthreads();
        if (c + 2 < 6) load_chunk(c + 2, (c & 1));
    }

    const int qrow = lane >> 2;
    const int qcol = (lane & 3) * 2;
#pragma unroll
    for (int mf = 0; mf < 2; mf++) {
#pragma unroll
        for (int nf = 0; nf < 4; nf++) {
            const int row = wm + mf * 16 + qrow;
            const int col = n0 + wn + nf * 8 + qcol;
            const float2 bb = *(const float2*)(bp + col);
            float* p0 = out + ((size_t)b * T + row) * HD + col;
            float* p1 = out + ((size_t)b * T + row + 8) * HD + col;
            *(float2*)p0 = make_float2(acc[mf][nf][0] + bb.x, acc[mf][nf][1] + bb.y);
            *(float2*)p1 = make_float2(acc[mf][nf][2] + bb.x, acc[mf][nf][3] + bb.y);
        }
    }
}

// =================================================================================
// MMA attention per (b, h): Q/K/V/P single fp16, fp32 accum.
// V loaded as a second cp.async group, overlapped with the S computation.
// smem: q@0 (16K), k@16K, v@32K => 48KB; 2 CTAs/SM.
// =================================================================================
#define ATTN_SMEM 49152

__global__ __launch_bounds__(256, 2)
void attn_mma()
{
    extern __shared__ __align__(1024) char sm[];
    const uint32_t smb = smem_u32(sm);
    const int tid = threadIdx.x, w = tid >> 5, lane = tid & 31;
    const int b = blockIdx.x, h = blockIdx.y;
    const int rb = (w < 4) ? w : (11 - w);     // row-block; SMSP pairs balanced

    const size_t blk = (size_t)(b * H + h) * (T * D);
    {
        const int seg = tid & 7;
#pragma unroll
        for (int p = 0; p < 4; p++) {
            const int row = (tid + p * 256) >> 3;          // 0..127
            const uint32_t doff = (uint32_t)(row * 128 + ((seg ^ (row & 7)) << 4));
            const size_t soff = blk + (size_t)row * D + seg * 8;
            cpa16(smb + doff,         g_q + soff);
            cpa16(smb + 16384 + doff, g_k + soff);
        }
        CPA_COMMIT();
#pragma unroll
        for (int p = 0; p < 4; p++) {
            const int row = (tid + p * 256) >> 3;
            const uint32_t doff = (uint32_t)(row * 128 + ((seg ^ (row & 7)) << 4));
            const size_t soff = blk + (size_t)row * D + seg * 8;
            cpa16(smb + 32768 + doff, g_v + soff);
        }
        CPA_COMMIT();
    }
    CPA_WAIT1();            // q,k complete; v still in flight
    __syncthreads();

    const int rA  = (lane & 7) + ((lane >> 3) & 1) * 8;
    const int khA = lane >> 4;
    const int swA = rA & 7;
    const int rB  = (lane & 7) + (lane >> 4) * 8;
    const int khB = (lane >> 3) & 1;
    const int swB = rB & 7;

    const uint32_t aQ = smb + (uint32_t)((rb * 16 + rA) * 128);

    // ---------------- S = Q @ K^T (single term, causal block-skip) ----------------
    float S[16][4];
#pragma unroll
    for (int i = 0; i < 16; i++)
#pragma unroll
        for (int e = 0; e < 4; e++) S[i][e] = 0.f;

#pragma unroll
    for (int ks = 0; ks < 4; ks++) {
        uint32_t qh[4];
        const uint32_t aoff = (uint32_t)(((ks * 2 + khA) ^ swA) << 4);
        ldsm4(qh, aQ + aoff);
        const uint32_t boff = (uint32_t)(((ks * 2 + khB) ^ swB) << 4);
#pragma unroll
        for (int g = 0; g < 8; g += 2) {
            if (g > rb) break;
            uint32_t kh0[4];
            const uint32_t bb0 = smb + 16384 + (uint32_t)((g * 16 + rB) * 128);
            ldsm4(kh0, bb0 + boff);
            const bool g1ok = (g + 1) <= rb;
            uint32_t kh1[4];
            if (g1ok) {
                const uint32_t bb1 = smb + 16384 + (uint32_t)(((g + 1) * 16 + rB) * 128);
                ldsm4(kh1, bb1 + boff);
            }
            mma16816f(S[2 * g],     qh, &kh0[0]);
            mma16816f(S[2 * g + 1], qh, &kh0[2]);
            if (g1ok) {
                mma16816f(S[2 * g + 2], qh, &kh1[0]);
                mma16816f(S[2 * g + 3], qh, &kh1[2]);
            }
        }
    }

    // ---------------- softmax exponentials (q pre-scaled by D^-1/2) ----------
    const int row0 = rb * 16 + (lane >> 2);
    const int row1 = row0 + 8;
    const int colb = 2 * (lane & 3);
    float sum0 = 0.f, sum1 = 0.f;
#pragma unroll
    for (int nf = 0; nf < 16; nf++) {
        if (nf > 2 * rb + 1) break;
        const int c0 = nf * 8 + colb, c1 = c0 + 1;
        float e00 = (c0 <= row0) ? __expf(S[nf][0]) : 0.f;
        float e01 = (c1 <= row0) ? __expf(S[nf][1]) : 0.f;
        float e10 = (c0 <= row1) ? __expf(S[nf][2]) : 0.f;
        float e11 = (c1 <= row1) ? __expf(S[nf][3]) : 0.f;
        S[nf][0] = e00; S[nf][1] = e01; S[nf][2] = e10; S[nf][3] = e11;
        sum0 += e00 + e01;
        sum1 += e10 + e11;
    }
    sum0 += __shfl_xor_sync(0xFFFFFFFFu, sum0, 1);
    sum0 += __shfl_xor_sync(0xFFFFFFFFu, sum0, 2);
    sum1 += __shfl_xor_sync(0xFFFFFFFFu, sum1, 1);
    sum1 += __shfl_xor_sync(0xFFFFFFFFu, sum1, 2);
    const float inv0 = 1.0f / sum0;
    const float inv1 = 1.0f / sum1;

    // v must be fully resident before ldmatrix reads it
    CPA_WAIT0();
    __syncthreads();

    // ---------------- O = (raw P) @ V ----------------
    float O[8][4];
#pragma unroll
    for (int i = 0; i < 8; i++)
#pragma unroll
        for (int e = 0; e < 4; e++) O[i][e] = 0.f;

    const int mT = lane >> 3;
    const int rT = lane & 7;

#pragma unroll
    for (int ks = 0; ks < 8; ks++) {
        if (ks > rb) break;
        const int srow = ks * 16 + (mT & 1) * 8 + rT;
        const uint32_t rowOff = (uint32_t)(srow * 128);
        uint32_t vh[4][4];
        {
            const int dseg0 = (mT >> 1);
            const uint32_t a0 = rowOff + (uint32_t)(((dseg0 ^ (srow & 7)) << 4));
            ldsm4t(vh[0], smb + 32768 + a0);
        }
        uint32_t phi[4];
        phi[0] = pack_f16x2(S[2 * ks][0],     S[2 * ks][1]);
        phi[1] = pack_f16x2(S[2 * ks][2],     S[2 * ks][3]);
        phi[2] = pack_f16x2(S[2 * ks + 1][0], S[2 * ks + 1][1]);
        phi[3] = pack_f16x2(S[2 * ks + 1][2], S[2 * ks + 1][3]);
#pragma unroll
        for (int g = 1; g < 4; g++) {
            const int dseg = g * 2 + (mT >> 1);
            const uint32_t addr = rowOff + (uint32_t)(((dseg ^ (srow & 7)) << 4));
            ldsm4t(vh[g], smb + 32768 + addr);
            mma16816f(O[2 * (g - 1)],     phi, &vh[g - 1][0]);
            mma16816f(O[2 * (g - 1) + 1], phi, &vh[g - 1][2]);
        }
        mma16816f(O[6], phi, &vh[3][0]);
        mma16816f(O[7], phi, &vh[3][2]);
    }

    // ---------------- epilogue: normalize, att fp16 [b][t][h*64+d] ---------
    const size_t obase = (size_t)b * T * HD + h * D;
#pragma unroll
    for (int nf = 0; nf < 8; nf++) {
        const int d0 = nf * 8 + colb;
        *(uint32_t*)(g_atthi + obase + (size_t)row0 * HD + d0) =
            pack_f16x2(O[nf][0] * inv0, O[nf][1] * inv0);
        *(uint32_t*)(g_atthi + obase + (size_t)row1 * HD + d0) =
            pack_f16x2(O[nf][2] * inv1, O[nf][3] * inv1);
    }
}

// =================================================================================
extern "C" void kernel_launch(void* const* d_in, const int* in_sizes, int n_in,
                              void* d_out, int out_size)
{
    (void)in_sizes; (void)n_in; (void)out_size;
    const float* x  = (const float*)d_in[0];
    const float* Wq = (const float*)d_in[1];
    const float* Wk = (const float*)d_in[2];
    const float* Wv = (const float*)d_in[3];
    const float* Wp = (const float*)d_in[4];
    const float* bp = (const float*)d_in[5];
    float* out = (float*)d_out;

    cudaFuncSetAttribute(qkv_gemm,  cudaFuncAttributeMaxDynamicSharedMemorySize, GEMM_SMEM);
    cudaFuncSetAttribute(proj_gemm, cudaFuncAttributeMaxDynamicSharedMemorySize, PROJ_SMEM);
    cudaFuncSetAttribute(attn_mma,  cudaFuncAttributeMaxDynamicSharedMemorySize, ATTN_SMEM);

    conv_all_kernel<<<NB_X + NB_W + NB_WP, 256>>>(x, Wq, Wk, Wv, Wp);

    qkv_gemm<<<dim3(9, BATCH), 256, GEMM_SMEM>>>();
    attn_mma<<<dim3(BATCH, H), 256, ATTN_SMEM>>>();
    proj_gemm<<<dim3(6, BATCH), 256, PROJ_SMEM>>>(bp, out);
}

// round 16
// speedup vs baseline: 1.0625x; 1.0185x over previous
#include <cuda_runtime.h>
#include <cuda_fp16.h>
#include <cstdint>

#define BATCH 512
#define T 128
#define C 384
#define H 6
#define D 64
#define HD 384
#define NQKV 1152

// ---------------- scratch (device globals; no runtime allocation) ----------------
__device__ __align__(256) __half g_xhi[(size_t)BATCH * T * C];
__device__ __align__(256) __half g_wthi[(size_t)NQKV * C];    // [n][k]
__device__ __align__(256) __half g_wpthi[(size_t)HD * C];     // [n][k] = Wp[k][n]
__device__ __align__(256) __half g_atthi[(size_t)BATCH * T * HD];
// q (pre-scaled D^-1/2), k, v single fp16; all [b][h][t][d]
__device__ __align__(256) __half g_q[(size_t)BATCH * H * T * D];
__device__ __align__(256) __half g_k[(size_t)BATCH * H * T * D];
__device__ __align__(256) __half g_v[(size_t)BATCH * H * T * D];

// ---------------- helpers (baseline PTX, compute_103-safe) ----------------
__device__ __forceinline__ uint32_t smem_u32(const void* p) {
    uint32_t a;
    asm("{ .reg .u64 t; cvta.to.shared.u64 t, %1; cvt.u32.u64 %0, t; }" : "=r"(a) : "l"(p));
    return a;
}
__device__ __forceinline__ void ldsm4(uint32_t* r, uint32_t addr) {
    asm volatile("ldmatrix.sync.aligned.m8n8.x4.shared.b16 {%0,%1,%2,%3}, [%4];"
        : "=r"(r[0]), "=r"(r[1]), "=r"(r[2]), "=r"(r[3]) : "r"(addr));
}
__device__ __forceinline__ void ldsm4t(uint32_t* r, uint32_t addr) {
    asm volatile("ldmatrix.sync.aligned.m8n8.x4.trans.shared.b16 {%0,%1,%2,%3}, [%4];"
        : "=r"(r[0]), "=r"(r[1]), "=r"(r[2]), "=r"(r[3]) : "r"(addr));
}
// fp16 MMA, fp32 accum
__device__ __forceinline__ void mma16816f(float* c, const uint32_t* a, const uint32_t* b) {
    asm volatile("mma.sync.aligned.m16n8k16.row.col.f32.f16.f16.f32 "
        "{%0,%1,%2,%3}, {%4,%5,%6,%7}, {%8,%9}, {%0,%1,%2,%3};"
        : "+f"(c[0]), "+f"(c[1]), "+f"(c[2]), "+f"(c[3])
        : "r"(a[0]), "r"(a[1]), "r"(a[2]), "r"(a[3]), "r"(b[0]), "r"(b[1]));
}
__device__ __forceinline__ void cpa16(uint32_t dst, const void* src) {
    asm volatile("cp.async.cg.shared.global [%0], [%1], 16;" :: "r"(dst), "l"(src));
}
#define CPA_COMMIT() asm volatile("cp.async.commit_group;" ::: "memory")
#define CPA_WAIT2()  asm volatile("cp.async.wait_group 2;" ::: "memory")
#define CPA_WAIT1()  asm volatile("cp.async.wait_group 1;" ::: "memory")
#define CPA_WAIT0()  asm volatile("cp.async.wait_group 0;" ::: "memory")

__device__ __forceinline__ uint32_t pack_f16x2(float a, float b) {
    __half2 h = __floats2half2_rn(a, b);
    return *(uint32_t*)&h;
}

// =================================================================================
// Fused conversion kernel. x-section: 16 floats/thread with 4 independent LDG.128
// in flight (MLP=4 hides DRAM latency). Then w and wp sections.
// =================================================================================
#define NB_X  ((BATCH * T * C / 16) / 256)         // 6144
#define NB_W  ((NQKV * C + 255) / 256)             // 1728
#define NB_WP ((HD * C + 255) / 256)               // 576

__global__ void conv_all_kernel(const float* __restrict__ x,
                                const float* __restrict__ Wq, const float* __restrict__ Wk,
                                const float* __restrict__ Wv, const float* __restrict__ Wp)
{
    const int bid = blockIdx.x;
    if (bid < NB_X) {
        // block covers 256*16 floats; thread t handles 4 float4s strided by 256
        const size_t base = (size_t)bid * (256 * 16) + threadIdx.x * 4;
        float4 v0 = *(const float4*)(x + base);
        float4 v1 = *(const float4*)(x + base + 1024);
        float4 v2 = *(const float4*)(x + base + 2048);
        float4 v3 = *(const float4*)(x + base + 3072);
        *(uint32_t*)(g_xhi + base)          = pack_f16x2(v0.x, v0.y);
        *(uint32_t*)(g_xhi + base + 2)      = pack_f16x2(v0.z, v0.w);
        *(uint32_t*)(g_xhi + base + 1024)   = pack_f16x2(v1.x, v1.y);
        *(uint32_t*)(g_xhi + base + 1026)   = pack_f16x2(v1.z, v1.w);
        *(uint32_t*)(g_xhi + base + 2048)   = pack_f16x2(v2.x, v2.y);
        *(uint32_t*)(g_xhi + base + 2050)   = pack_f16x2(v2.z, v2.w);
        *(uint32_t*)(g_xhi + base + 3072)   = pack_f16x2(v3.x, v3.y);
        *(uint32_t*)(g_xhi + base + 3074)   = pack_f16x2(v3.z, v3.w);
    } else if (bid < NB_X + NB_W) {
        int idx = (bid - NB_X) * 256 + threadIdx.x;   // n*C + k
        if (idx >= NQKV * C) return;
        int n = idx / C, k = idx - n * C;
        int which = n / HD, rem = n - which * HD;
        int h = rem >> 6, d = rem & 63;
        const float* W = (which == 0) ? Wq : (which == 1) ? Wk : Wv;
        g_wthi[idx] = __float2half_rn(W[((size_t)h * C + k) * D + d]);
    } else {
        int idx = (bid - NB_X - NB_W) * 256 + threadIdx.x;   // n*C + k
        if (idx >= HD * C) return;
        int n = idx / C, k = idx - n * C;
        g_wpthi[idx] = __float2half_rn(Wp[(size_t)k * C + n]);
    }
}

// =================================================================================
// QKV GEMM: Y[128x128] = x[128x384] @ wt^T, 3-stage pipeline,
// stage 32KB, 2 CTAs/SM, grid (9, BATCH).
// =================================================================================
#define STAGE_BYTES 32768
#define GEMM_SMEM (3 * STAGE_BYTES)

__global__ __launch_bounds__(256, 2)
void qkv_gemm()
{
    extern __shared__ __align__(1024) char sm[];
    const uint32_t smb = smem_u32(sm);
    const int tid = threadIdx.x, wid = tid >> 5, lane = tid & 31;
    const int b = blockIdx.y, n0 = blockIdx.x * 128;
    const int wm = (wid >> 2) * 64;     // 0,64
    const int wn = (wid & 3) * 32;      // 0,32,64,96

    const __half* __restrict__ Ahi = g_xhi + (size_t)b * T * C;
    const __half* __restrict__ Bhi = g_wthi + (size_t)n0 * C;

    const int l_row = tid >> 3;
    const int l_seg = tid & 7;

    auto load_chunk = [&](int c) {
        const int c0 = c * 64;
        const uint32_t sb = smb + (c % 3) * STAGE_BYTES;
#pragma unroll
        for (int p = 0; p < 4; p++) {
            const int row = l_row + p * 32;
            const uint32_t doff = (uint32_t)(row * 128 + ((l_seg ^ (row & 7)) << 4));
            const size_t soff = (size_t)row * C + c0 + l_seg * 8;
            cpa16(sb + doff,         Ahi + soff);
            cpa16(sb + 16384 + doff, Bhi + soff);
        }
        CPA_COMMIT();
    };

    float acc[4][4][4];
#pragma unroll
    for (int i = 0; i < 4; i++)
#pragma unroll
        for (int j = 0; j < 4; j++)
#pragma unroll
            for (int e = 0; e < 4; e++) acc[i][j][e] = 0.f;

    const int rA  = (lane & 7) + ((lane >> 3) & 1) * 8;
    const int khA = lane >> 4;
    const int swA = rA & 7;
    const int rB  = (lane & 7) + (lane >> 4) * 8;
    const int khB = (lane >> 3) & 1;
    const int swB = rB & 7;

    load_chunk(0);
    load_chunk(1);
    load_chunk(2);

    for (int c = 0; c < 6; c++) {
        if (c < 4) CPA_WAIT2(); else if (c == 4) CPA_WAIT1(); else CPA_WAIT0();
        __syncthreads();

        const uint32_t sb = smb + (c % 3) * STAGE_BYTES;
        const uint32_t aBase = sb + (uint32_t)((wm + rA) * 128);
        const uint32_t bBase = sb + 16384 + (uint32_t)((wn + rB) * 128);

#pragma unroll
        for (int ks = 0; ks < 4; ks++) {
            const uint32_t aoff = (uint32_t)(((ks * 2 + khA) ^ swA) << 4);
            const uint32_t boff = (uint32_t)(((ks * 2 + khB) ^ swB) << 4);
            uint32_t ah[4][4], bh[2][4];
            ldsm4(ah[0], aBase + aoff);
            ldsm4(bh[0], bBase + boff);
            ldsm4(ah[1], aBase + 2048 + aoff);
            ldsm4(bh[1], bBase + 2048 + boff);
            mma16816f(acc[0][0], ah[0], &bh[0][0]);
            mma16816f(acc[0][1], ah[0], &bh[0][2]);
            ldsm4(ah[2], aBase + 4096 + aoff);
            mma16816f(acc[0][2], ah[0], &bh[1][0]);
            mma16816f(acc[0][3], ah[0], &bh[1][2]);
            ldsm4(ah[3], aBase + 6144 + aoff);
            mma16816f(acc[1][0], ah[1], &bh[0][0]);
            mma16816f(acc[1][1], ah[1], &bh[0][2]);
            mma16816f(acc[1][2], ah[1], &bh[1][0]);
            mma16816f(acc[1][3], ah[1], &bh[1][2]);
#pragma unroll
            for (int mf = 2; mf < 4; mf++) {
                mma16816f(acc[mf][0], ah[mf], &bh[0][0]);
                mma16816f(acc[mf][1], ah[mf], &bh[0][2]);
                mma16816f(acc[mf][2], ah[mf], &bh[1][0]);
                mma16816f(acc[mf][3], ah[mf], &bh[1][2]);
            }
        }
        __syncthreads();
        if (c + 3 < 6) load_chunk(c + 3);
    }

    const int qrow = lane >> 2;
    const int qcol = (lane & 3) * 2;
    const int which = blockIdx.x / 3;       // 0=q,1=k,2=v
    const int rem0 = (blockIdx.x % 3) * 128;
    __half* dst = (which == 0) ? g_q : (which == 1) ? g_k : g_v;
    const float scale = (which == 0) ? 0.125f : 1.0f;
#pragma unroll
    for (int mf = 0; mf < 4; mf++) {
#pragma unroll
        for (int nf = 0; nf < 4; nf++) {
            const int row = wm + mf * 16 + qrow;
            const int rem = rem0 + wn + nf * 8 + qcol;
            const int hh = rem >> 6, dd = rem & 63;
            const size_t o0 = (((size_t)(b * H + hh) * T) + row) * D + dd;
            *(uint32_t*)(dst + o0) =
                pack_f16x2(acc[mf][nf][0] * scale, acc[mf][nf][1] * scale);
            *(uint32_t*)(dst + o0 + 8 * D) =
                pack_f16x2(acc[mf][nf][2] * scale, acc[mf][nf][3] * scale);
        }
    }
}

// =================================================================================
// Proj GEMM: Y[128x64] = att[128x384] @ wpt^T + bias.
// Stage 24KB (A16K, B8K), 2 stages = 48KB, 3 CTAs/SM, grid (6, BATCH).
// =================================================================================
#define PSTAGE_BYTES 24576
#define PROJ_SMEM (2 * PSTAGE_BYTES)

__global__ __launch_bounds__(256, 3)
void proj_gemm(const float* __restrict__ bp, float* __restrict__ out)
{
    extern __shared__ __align__(1024) char sm[];
    const uint32_t smb = smem_u32(sm);
    const int tid = threadIdx.x, wid = tid >> 5, lane = tid & 31;
    const int b = blockIdx.y, n0 = blockIdx.x * 64;
    const int wm = (wid >> 1) * 32;     // 0,32,64,96
    const int wn = (wid & 1) * 32;      // 0,32

    const __half* __restrict__ Ahi = g_atthi + (size_t)b * T * C;
    const __half* __restrict__ Bhi = g_wpthi + (size_t)n0 * C;

    const int l_row = tid >> 3;
    const int l_seg = tid & 7;

    auto load_chunk = [&](int c, int s) {
        const int c0 = c * 64;
        const uint32_t sb = smb + s * PSTAGE_BYTES;
#pragma unroll
        for (int p = 0; p < 4; p++) {
            const int row = l_row + p * 32;
            const uint32_t doff = (uint32_t)(row * 128 + ((l_seg ^ (row & 7)) << 4));
            cpa16(sb + doff, Ahi + (size_t)row * C + c0 + l_seg * 8);
        }
#pragma unroll
        for (int p = 0; p < 2; p++) {
            const int row = l_row + p * 32;   // 0..63
            const uint32_t doff = (uint32_t)(row * 128 + ((l_seg ^ (row & 7)) << 4));
            cpa16(sb + 16384 + doff, Bhi + (size_t)row * C + c0 + l_seg * 8);
        }
        CPA_COMMIT();
    };

    float acc[2][4][4];
#pragma unroll
    for (int i = 0; i < 2; i++)
#pragma unroll
        for (int j = 0; j < 4; j++)
#pragma unroll
            for (int e = 0; e < 4; e++) acc[i][j][e] = 0.f;

    const int rA  = (lane & 7) + ((lane >> 3) & 1) * 8;
    const int khA = lane >> 4;
    const int swA = rA & 7;
    const int rB  = (lane & 7) + (lane >> 4) * 8;
    const int khB = (lane >> 3) & 1;
    const int swB = rB & 7;

    load_chunk(0, 0);
    load_chunk(1, 1);

    for (int c = 0; c < 6; c++) {
        if (c == 5) CPA_WAIT0(); else CPA_WAIT1();
        __syncthreads();

        const uint32_t sb = smb + (c & 1) * PSTAGE_BYTES;
        const uint32_t aBase = sb + (uint32_t)((wm + rA) * 128);
        const uint32_t bBase = sb + 16384 + (uint32_t)((wn + rB) * 128);

#pragma unroll
        for (int ks = 0; ks < 4; ks++) {
            const uint32_t aoff = (uint32_t)(((ks * 2 + khA) ^ swA) << 4);
            const uint32_t boff = (uint32_t)(((ks * 2 + khB) ^ swB) << 4);
            uint32_t ah[2][4], bh[2][4];
            ldsm4(ah[0], aBase + aoff);
            ldsm4(bh[0], bBase + boff);
            ldsm4(ah[1], aBase + 2048 + aoff);
            ldsm4(bh[1], bBase + 2048 + boff);
            mma16816f(acc[0][0], ah[0], &bh[0][0]);
            mma16816f(acc[0][1], ah[0], &bh[0][2]);
            mma16816f(acc[0][2], ah[0], &bh[1][0]);
            mma16816f(acc[0][3], ah[0], &bh[1][2]);
            mma16816f(acc[1][0], ah[1], &bh[0][0]);
            mma16816f(acc[1][1], ah[1], &bh[0][2]);
            mma16816f(acc[1][2], ah[1], &bh[1][0]);
            mma16816f(acc[1][3], ah[1], &bh[1][2]);
        }
        __syncthreads();
        if (c + 2 < 6) load_chunk(c + 2, (c & 1));
    }

    const int qrow = lane >> 2;
    const int qcol = (lane & 3) * 2;
#pragma unroll
    for (int mf = 0; mf < 2; mf++) {
#pragma unroll
        for (int nf = 0; nf < 4; nf++) {
            const int row = wm + mf * 16 + qrow;
            const int col = n0 + wn + nf * 8 + qcol;
            const float2 bb = *(const float2*)(bp + col);
            float* p0 = out + ((size_t)b * T + row) * HD + col;
            float* p1 = out + ((size_t)b * T + row + 8) * HD + col;
            *(float2*)p0 = make_float2(acc[mf][nf][0] + bb.x, acc[mf][nf][1] + bb.y);
            *(float2*)p1 = make_float2(acc[mf][nf][2] + bb.x, acc[mf][nf][3] + bb.y);
        }
    }
}

// =================================================================================
// MMA attention per (b, h): Q/K/V/P single fp16, fp32 accum.
// V loaded as a second cp.async group, overlapped with the S computation.
// smem: q@0 (16K), k@16K, v@32K => 48KB; 2 CTAs/SM.
// =================================================================================
#define ATTN_SMEM 49152

__global__ __launch_bounds__(256, 2)
void attn_mma()
{
    extern __shared__ __align__(1024) char sm[];
    const uint32_t smb = smem_u32(sm);
    const int tid = threadIdx.x, w = tid >> 5, lane = tid & 31;
    const int b = blockIdx.x, h = blockIdx.y;
    const int rb = (w < 4) ? w : (11 - w);     // row-block; SMSP pairs balanced

    const size_t blk = (size_t)(b * H + h) * (T * D);
    {
        const int seg = tid & 7;
#pragma unroll
        for (int p = 0; p < 4; p++) {
            const int row = (tid + p * 256) >> 3;          // 0..127
            const uint32_t doff = (uint32_t)(row * 128 + ((seg ^ (row & 7)) << 4));
            const size_t soff = blk + (size_t)row * D + seg * 8;
            cpa16(smb + doff,         g_q + soff);
            cpa16(smb + 16384 + doff, g_k + soff);
        }
        CPA_COMMIT();
#pragma unroll
        for (int p = 0; p < 4; p++) {
            const int row = (tid + p * 256) >> 3;
            const uint32_t doff = (uint32_t)(row * 128 + ((seg ^ (row & 7)) << 4));
            const size_t soff = blk + (size_t)row * D + seg * 8;
            cpa16(smb + 32768 + doff, g_v + soff);
        }
        CPA_COMMIT();
    }
    CPA_WAIT1();            // q,k complete; v still in flight
    __syncthreads();

    const int rA  = (lane & 7) + ((lane >> 3) & 1) * 8;
    const int khA = lane >> 4;
    const int swA = rA & 7;
    const int rB  = (lane & 7) + (lane >> 4) * 8;
    const int khB = (lane >> 3) & 1;
    const int swB = rB & 7;

    const uint32_t aQ = smb + (uint32_t)((rb * 16 + rA) * 128);

    // ---------------- S = Q @ K^T (single term, causal block-skip) ----------------
    float S[16][4];
#pragma unroll
    for (int i = 0; i < 16; i++)
#pragma unroll
        for (int e = 0; e < 4; e++) S[i][e] = 0.f;

#pragma unroll
    for (int ks = 0; ks < 4; ks++) {
        uint32_t qh[4];
        const uint32_t aoff = (uint32_t)(((ks * 2 + khA) ^ swA) << 4);
        ldsm4(qh, aQ + aoff);
        const uint32_t boff = (uint32_t)(((ks * 2 + khB) ^ swB) << 4);
#pragma unroll
        for (int g = 0; g < 8; g += 2) {
            if (g > rb) break;
            uint32_t kh0[4];
            const uint32_t bb0 = smb + 16384 + (uint32_t)((g * 16 + rB) * 128);
            ldsm4(kh0, bb0 + boff);
            const bool g1ok = (g + 1) <= rb;
            uint32_t kh1[4];
            if (g1ok) {
                const uint32_t bb1 = smb + 16384 + (uint32_t)(((g + 1) * 16 + rB) * 128);
                ldsm4(kh1, bb1 + boff);
            }
            mma16816f(S[2 * g],     qh, &kh0[0]);
            mma16816f(S[2 * g + 1], qh, &kh0[2]);
            if (g1ok) {
                mma16816f(S[2 * g + 2], qh, &kh1[0]);
                mma16816f(S[2 * g + 3], qh, &kh1[2]);
            }
        }
    }

    // ---------------- softmax exponentials (q pre-scaled by D^-1/2) ----------
    const int row0 = rb * 16 + (lane >> 2);
    const int row1 = row0 + 8;
    const int colb = 2 * (lane & 3);
    float sum0 = 0.f, sum1 = 0.f;
#pragma unroll
    for (int nf = 0; nf < 16; nf++) {
        if (nf > 2 * rb + 1) break;
        const int c0 = nf * 8 + colb, c1 = c0 + 1;
        float e00 = (c0 <= row0) ? __expf(S[nf][0]) : 0.f;
        float e01 = (c1 <= row0) ? __expf(S[nf][1]) : 0.f;
        float e10 = (c0 <= row1) ? __expf(S[nf][2]) : 0.f;
        float e11 = (c1 <= row1) ? __expf(S[nf][3]) : 0.f;
        S[nf][0] = e00; S[nf][1] = e01; S[nf][2] = e10; S[nf][3] = e11;
        sum0 += e00 + e01;
        sum1 += e10 + e11;
    }
    sum0 += __shfl_xor_sync(0xFFFFFFFFu, sum0, 1);
    sum0 += __shfl_xor_sync(0xFFFFFFFFu, sum0, 2);
    sum1 += __shfl_xor_sync(0xFFFFFFFFu, sum1, 1);
    sum1 += __shfl_xor_sync(0xFFFFFFFFu, sum1, 2);
    const float inv0 = 1.0f / sum0;
    const float inv1 = 1.0f / sum1;

    // v must be fully resident before ldmatrix reads it
    CPA_WAIT0();
    __syncthreads();

    // ---------------- O = (raw P) @ V ----------------
    float O[8][4];
#pragma unroll
    for (int i = 0; i < 8; i++)
#pragma unroll
        for (int e = 0; e < 4; e++) O[i][e] = 0.f;

    const int mT = lane >> 3;
    const int rT = lane & 7;

#pragma unroll
    for (int ks = 0; ks < 8; ks++) {
        if (ks > rb) break;
        const int srow = ks * 16 + (mT & 1) * 8 + rT;
        const uint32_t rowOff = (uint32_t)(srow * 128);
        uint32_t vh[4][4];
        {
            const int dseg0 = (mT >> 1);
            const uint32_t a0 = rowOff + (uint32_t)(((dseg0 ^ (srow & 7)) << 4));
            ldsm4t(vh[0], smb + 32768 + a0);
        }
        uint32_t phi[4];
        phi[0] = pack_f16x2(S[2 * ks][0],     S[2 * ks][1]);
        phi[1] = pack_f16x2(S[2 * ks][2],     S[2 * ks][3]);
        phi[2] = pack_f16x2(S[2 * ks + 1][0], S[2 * ks + 1][1]);
        phi[3] = pack_f16x2(S[2 * ks + 1][2], S[2 * ks + 1][3]);
#pragma unroll
        for (int g = 1; g < 4; g++) {
            const int dseg = g * 2 + (mT >> 1);
            const uint32_t addr = rowOff + (uint32_t)(((dseg ^ (srow & 7)) << 4));
            ldsm4t(vh[g], smb + 32768 + addr);
            mma16816f(O[2 * (g - 1)],     phi, &vh[g - 1][0]);
            mma16816f(O[2 * (g - 1) + 1], phi, &vh[g - 1][2]);
        }
        mma16816f(O[6], phi, &vh[3][0]);
        mma16816f(O[7], phi, &vh[3][2]);
    }

    // ---------------- epilogue: normalize, att fp16 [b][t][h*64+d] ---------
    const size_t obase = (size_t)b * T * HD + h * D;
#pragma unroll
    for (int nf = 0; nf < 8; nf++) {
        const int d0 = nf * 8 + colb;
        *(uint32_t*)(g_atthi + obase + (size_t)row0 * HD + d0) =
            pack_f16x2(O[nf][0] * inv0, O[nf][1] * inv0);
        *(uint32_t*)(g_atthi + obase + (size_t)row1 * HD + d0) =
            pack_f16x2(O[nf][2] * inv1, O[nf][3] * inv1);
    }
}

// =================================================================================
extern "C" void kernel_launch(void* const* d_in, const int* in_sizes, int n_in,
                              void* d_out, int out_size)
{
    (void)in_sizes; (void)n_in; (void)out_size;
    const float* x  = (const float*)d_in[0];
    const float* Wq = (const float*)d_in[1];
    const float* Wk = (const float*)d_in[2];
    const float* Wv = (const float*)d_in[3];
    const float* Wp = (const float*)d_in[4];
    const float* bp = (const float*)d_in[5];
    float* out = (float*)d_out;

    cudaFuncSetAttribute(qkv_gemm,  cudaFuncAttributeMaxDynamicSharedMemorySize, GEMM_SMEM);
    cudaFuncSetAttribute(proj_gemm, cudaFuncAttributeMaxDynamicSharedMemorySize, PROJ_SMEM);
    cudaFuncSetAttribute(attn_mma,  cudaFuncAttributeMaxDynamicSharedMemorySize, ATTN_SMEM);

    conv_all_kernel<<<NB_X + NB_W + NB_WP, 256>>>(x, Wq, Wk, Wv, Wp);

    qkv_gemm<<<dim3(9, BATCH), 256, GEMM_SMEM>>>();
    attn_mma<<<dim3(BATCH, H), 256, ATTN_SMEM>>>();
    proj_gemm<<<dim3(6, BATCH), 256, PROJ_SMEM>>>(bp, out);
}